// round 7
// baseline (speedup 1.0000x reference)
#include <cuda_runtime.h>
#include <cstdint>

#define BB 2
#define NN 8192
#define CC 80
#define KCAP 128
#define NMS_BLOCKS 16
#define RC 12            /* suppressor entries cached in registers */
#define MAXIT 48

typedef unsigned long long u64;
typedef unsigned int u32;
typedef unsigned short u16;
typedef unsigned char u8;

/* output layout (concatenated flat float32, tuple order) */
#define OFF_BOXES 0
#define OFF_MS    (BB*NN*4)
#define OFF_LB    (OFF_MS + BB*NN)
#define OFF_KEEP  (OFF_LB + BB*NN)
#define OFF_ALL   (OFF_KEEP + BB*NN)

/* static device scratch */
__device__ u32   g_key32[BB][NN];      /* ~score_bits; smaller = higher prio */
__device__ float g_area[BB][NN];
__device__ u8    g_validb[BB][NN];
__device__ u8    g_keep[BB * NN];      /* flat, volatile-accessed in nms */
__device__ int   g_cnt[BB][NN];
__device__ u16   g_list[BB][NN][KCAP];
__device__ int   g_changed[MAXIT];
__device__ u32   g_bar;

/* ------------------------------------------------------------------ */
/* Kernel 1: sigmoid / max / argmax / decode / valid / init of flags   */
__global__ void prep_kernel(const float* __restrict__ logits,
                            const float* __restrict__ deltas,
                            const float* __restrict__ anchors,
                            float* __restrict__ out)
{
    int wid  = (blockIdx.x * blockDim.x + threadIdx.x) >> 5;
    int lane = threadIdx.x & 31;
    if (wid >= BB * NN) return;
    int b = wid / NN, n = wid % NN;

    /* folded init work (spread across lanes) */
    if (lane == 1) g_cnt[b][n] = 0;
    if (wid < MAXIT && lane == 2) g_changed[wid] = 0;
    if (wid == 0 && lane == 3) g_bar = 0;

    const float4* lg4 = (const float4*)(logits + (size_t)wid * CC);
    float4* as4       = (float4*)(out + OFF_ALL + (size_t)wid * CC);

    float mv = -INFINITY; int mi = 0;
    if (lane < 20) {
        float4 v = lg4[lane];
        /* bulk sigmoid: __expf + __fdividef (2 ulp) */
        float4 s;
        s.x = __fdividef(1.0f, 1.0f + __expf(-v.x));
        s.y = __fdividef(1.0f, 1.0f + __expf(-v.y));
        s.z = __fdividef(1.0f, 1.0f + __expf(-v.z));
        s.w = __fdividef(1.0f, 1.0f + __expf(-v.w));
        as4[lane] = s;

        mv = v.x; mi = lane * 4;
        if (v.y > mv) { mv = v.y; mi = lane * 4 + 1; }
        if (v.z > mv) { mv = v.z; mi = lane * 4 + 2; }
        if (v.w > mv) { mv = v.w; mi = lane * 4 + 3; }
    }

    for (int off = 16; off; off >>= 1) {
        float ov = __shfl_down_sync(0xffffffffu, mv, off);
        int   oi = __shfl_down_sync(0xffffffffu, mi, off);
        if (ov > mv || (ov == mv && oi < mi)) { mv = ov; mi = oi; }
    }

    if (lane == 0) {
        float ms = 1.0f / (1.0f + expf(-mv));   /* accurate for thresholds */
        out[OFF_MS + wid] = ms;
        out[OFF_LB + wid] = (float)mi;

        const float* dl = deltas  + (size_t)wid * 4;
        const float* an = anchors + (size_t)n * 4;
        float a0 = an[0], a1 = an[1], a2 = an[2], a3 = an[3];
        float aw = a2 - a0, ah = a3 - a1;
        float acx = a0 + 0.5f * aw, acy = a1 + 0.5f * ah;
        float dx = dl[0], dy = dl[1];
        float dw = fminf(dl[2], 4.0f), dh = fminf(dl[3], 4.0f);
        float pcx = dx * aw + acx, pcy = dy * ah + acy;
        float pw = expf(dw) * aw, ph = expf(dh) * ah;
        float x1 = fminf(fmaxf(pcx - 0.5f * pw, 0.0f), 1.0f);
        float y1 = fminf(fmaxf(pcy - 0.5f * ph, 0.0f), 1.0f);
        float x2 = fminf(fmaxf(pcx + 0.5f * pw, 0.0f), 1.0f);
        float y2 = fminf(fmaxf(pcy + 0.5f * ph, 0.0f), 1.0f);

        float* bo = out + OFF_BOXES + (size_t)wid * 4;
        bo[0] = x1; bo[1] = y1; bo[2] = x2; bo[3] = y2;

        float w = x2 - x1, h = y2 - y1;
        u8 valid = (ms > 0.5f) && (w > 0.01f) && (h > 0.01f) &&
                   (w < 0.99f) && (h < 0.99f);
        g_validb[b][n] = valid;
        g_keep[b * NN + n] = valid;
        g_area[b][n] = w * h;
        g_key32[b][n] = ~__float_as_uint(ms);
    }
}

/* ------------------------------------------------------------------ */
/* Kernel 2: sparse suppressor pairs, original order, early-outs.      */
/* Block: col tile cb (64 boxes in smem) x 4 row tiles (256 threads).  */
__global__ void pairs_kernel(const float* __restrict__ out)
{
    int cb = blockIdx.x, rbg = blockIdx.y, b = blockIdx.z;
    if (rbg * 4 > cb) return;             /* whole block above diagonal */
    int t = threadIdx.x;                  /* 256 */

    __shared__ float sx1[64], sy1[64], sx2[64], sy2[64], sar[64];
    __shared__ u32 skey[64];

    if (t < 64) {
        int cj = cb * 64 + t;
        float4 cbx = *(const float4*)(out + OFF_BOXES + ((size_t)b * NN + cj) * 4);
        sx1[t] = cbx.x; sy1[t] = cbx.y; sx2[t] = cbx.z; sy2[t] = cbx.w;
        sar[t] = g_area[b][cj];
        skey[t] = g_key32[b][cj];
    }
    __syncthreads();

    int i = rbg * 256 + t;                /* global row box index */
    int rowtile = i >> 6;
    if (rowtile > cb) return;             /* after sync: safe */

    float4 rbx = *(const float4*)(out + OFF_BOXES + ((size_t)b * NN + i) * 4);
    float ar = g_area[b][i];
    u32  kr = g_key32[b][i];
    float arh = 0.499f * ar, ar2 = 2.005f * ar;   /* safety-margined bounds */

    int jstart = (rowtile == cb) ? (i & 63) + 1 : 0;
    for (int j = jstart; j < 64; j++) {
        float aj = sar[j];
        if (aj < arh || aj > ar2) continue;        /* IoU <= min/max areas */
        float ix1 = fmaxf(rbx.x, sx1[j]);
        float ix2 = fminf(rbx.z, sx2[j]);
        if (ix2 <= ix1) continue;
        float iy1 = fmaxf(rbx.y, sy1[j]);
        float iy2 = fminf(rbx.w, sy2[j]);
        if (iy2 <= iy1) continue;
        float inter = (ix2 - ix1) * (iy2 - iy1);
        float uni = ar + aj - inter;
        if (inter > 0.5f * fmaxf(uni, 1e-9f)) {
            int cj = cb * 64 + j;
            u32 kj = skey[j];
            bool jwins = (kj < kr) || (kj == kr && cj < i);
            int victim = jwins ? i : cj;
            int supp   = jwins ? cj : i;
            int pos = atomicAdd(&g_cnt[b][victim], 1);
            if (pos < KCAP) g_list[b][victim][pos] = (u16)supp;
        }
    }
}

/* ------------------------------------------------------------------ */
/* Kernel 3: parallel greedy-NMS fixed point. 16 blocks, 1 thread/box. */
/* Register-cached lists, volatile keep, 2 updates per grid barrier.   */
__global__ __launch_bounds__(1024, 2)
void nms_kernel(float* __restrict__ out)
{
    int t = blockIdx.x * 1024 + threadIdx.x;   /* 0 .. 16383 */
    int b = t >> 13;
    int i = t & (NN - 1);

    u8 valid = g_validb[b][i];
    int cnt = valid ? min(g_cnt[b][i], KCAP) : 0;

    volatile u8* kp = g_keep;
    const u16* lp = g_list[b][i];

    /* cache first RC suppressors as flat indices (dup-pad with last) */
    int lf[RC];
    int nr = 0, restn = 0;
    if (cnt > 0) {
        nr = min(cnt, RC);
        restn = cnt - nr;
        int last = b * NN + (int)lp[nr - 1];
#pragma unroll
        for (int q = 0; q < RC; q++)
            lf[q] = (q < nr) ? (b * NN + (int)lp[q]) : last;
    }

    __shared__ int s_stop;
    u32 tgt = 0;
    u8 cur = valid;

    for (int it = 0; it < MAXIT; it++) {
        bool ch = false;
        if (cnt > 0) {
#pragma unroll
            for (int rep = 0; rep < 2; rep++) {
                u32 s = 0;
#pragma unroll
                for (int q = 0; q < RC; q++) s |= kp[lf[q]];
                for (int q = 0; q < restn; q++)
                    s |= kp[b * NN + (int)lp[RC + q]];
                u8 nk = (u8)(s == 0);       /* valid==1 on this path */
                if (nk != cur) { cur = nk; kp[b * NN + i] = nk; ch = true; }
            }
        }

        u32 w = __ballot_sync(0xffffffffu, ch);
        if ((threadIdx.x & 31) == 0 && w) g_changed[it] = 1;
        __threadfence();

        __syncthreads();
        tgt += NMS_BLOCKS;
        if (threadIdx.x == 0) {
            atomicAdd(&g_bar, 1u);
            while (*((volatile u32*)&g_bar) < tgt) __nanosleep(64);
            s_stop = (*((volatile int*)&g_changed[it]) == 0);
        }
        __syncthreads();
        if (s_stop) break;
    }

    out[OFF_KEEP + b * NN + i] = (float)cur;
}

/* ------------------------------------------------------------------ */
extern "C" void kernel_launch(void* const* d_in, const int* in_sizes, int n_in,
                              void* d_out, int out_size)
{
    (void)in_sizes; (void)n_in; (void)out_size;
    const float* logits  = (const float*)d_in[0];
    const float* deltas  = (const float*)d_in[1];
    const float* anchors = (const float*)d_in[2];
    float* out = (float*)d_out;

    prep_kernel<<<(BB * NN * 32 + 255) / 256, 256>>>(logits, deltas, anchors, out);
    {
        dim3 g(NN / 64, 32, BB);   /* col tile x row-tile group x batch */
        pairs_kernel<<<g, 256>>>(out);
    }
    nms_kernel<<<NMS_BLOCKS, 1024>>>(out);
}

// round 8
// speedup vs baseline: 1.2394x; 1.2394x over previous
#include <cuda_runtime.h>
#include <cstdint>

#define BB 2
#define NN 8192
#define CC 80
#define KCAP 128
#define MAXIT 64

typedef unsigned long long u64;
typedef unsigned int u32;
typedef unsigned short u16;
typedef unsigned char u8;

/* output layout (concatenated flat float32, tuple order) */
#define OFF_BOXES 0
#define OFF_MS    (BB*NN*4)
#define OFF_LB    (OFF_MS + BB*NN)
#define OFF_KEEP  (OFF_LB + BB*NN)
#define OFF_ALL   (OFF_KEEP + BB*NN)

/* static device scratch */
__device__ u32   g_key32[BB][NN];     /* ~score_bits; smaller = higher prio */
__device__ float g_area[BB][NN];
__device__ u8    g_validb[BB][NN];
__device__ int   g_cnt[BB][NN];
__device__ u16   g_list[BB][NN][KCAP];

/* ------------------------------------------------------------------ */
/* Kernel 1: sigmoid / max / argmax / decode / valid (+ folded init)   */
__global__ void prep_kernel(const float* __restrict__ logits,
                            const float* __restrict__ deltas,
                            const float* __restrict__ anchors,
                            float* __restrict__ out)
{
    int wid  = (blockIdx.x * blockDim.x + threadIdx.x) >> 5;
    int lane = threadIdx.x & 31;
    if (wid >= BB * NN) return;
    int b = wid / NN, n = wid % NN;

    if (lane == 1) g_cnt[b][n] = 0;

    const float4* lg4 = (const float4*)(logits + (size_t)wid * CC);
    float4* as4       = (float4*)(out + OFF_ALL + (size_t)wid * CC);

    float mv = -INFINITY; int mi = 0;
    if (lane < 20) {
        float4 v = lg4[lane];
        float4 s;
        s.x = __fdividef(1.0f, 1.0f + __expf(-v.x));
        s.y = __fdividef(1.0f, 1.0f + __expf(-v.y));
        s.z = __fdividef(1.0f, 1.0f + __expf(-v.z));
        s.w = __fdividef(1.0f, 1.0f + __expf(-v.w));
        as4[lane] = s;

        mv = v.x; mi = lane * 4;
        if (v.y > mv) { mv = v.y; mi = lane * 4 + 1; }
        if (v.z > mv) { mv = v.z; mi = lane * 4 + 2; }
        if (v.w > mv) { mv = v.w; mi = lane * 4 + 3; }
    }

    for (int off = 16; off; off >>= 1) {
        float ov = __shfl_down_sync(0xffffffffu, mv, off);
        int   oi = __shfl_down_sync(0xffffffffu, mi, off);
        if (ov > mv || (ov == mv && oi < mi)) { mv = ov; mi = oi; }
    }

    if (lane == 0) {
        float ms = 1.0f / (1.0f + expf(-mv));   /* accurate at threshold */
        out[OFF_MS + wid] = ms;
        out[OFF_LB + wid] = (float)mi;

        const float* dl = deltas  + (size_t)wid * 4;
        const float* an = anchors + (size_t)n * 4;
        float a0 = an[0], a1 = an[1], a2 = an[2], a3 = an[3];
        float aw = a2 - a0, ah = a3 - a1;
        float acx = a0 + 0.5f * aw, acy = a1 + 0.5f * ah;
        float dx = dl[0], dy = dl[1];
        float dw = fminf(dl[2], 4.0f), dh = fminf(dl[3], 4.0f);
        float pcx = dx * aw + acx, pcy = dy * ah + acy;
        float pw = expf(dw) * aw, ph = expf(dh) * ah;
        float x1 = fminf(fmaxf(pcx - 0.5f * pw, 0.0f), 1.0f);
        float y1 = fminf(fmaxf(pcy - 0.5f * ph, 0.0f), 1.0f);
        float x2 = fminf(fmaxf(pcx + 0.5f * pw, 0.0f), 1.0f);
        float y2 = fminf(fmaxf(pcy + 0.5f * ph, 0.0f), 1.0f);

        float* bo = out + OFF_BOXES + (size_t)wid * 4;
        bo[0] = x1; bo[1] = y1; bo[2] = x2; bo[3] = y2;

        float w = x2 - x1, h = y2 - y1;
        u8 valid = (ms > 0.5f) && (w > 0.01f) && (h > 0.01f) &&
                   (w < 0.99f) && (h < 0.99f);
        g_validb[b][n] = valid;
        g_area[b][n] = w * h;
        g_key32[b][n] = ~__float_as_uint(ms);
    }
}

/* ------------------------------------------------------------------ */
/* Kernel 2: sparse suppressor pairs, original order, straight-line.   */
/* Only pairs where BOTH boxes valid are recorded (keep subset valid). */
__global__ void pairs_kernel(const float* __restrict__ out)
{
    int b = blockIdx.y;
    int L = blockIdx.x;
    int cb = (int)((sqrtf(8.0f * (float)L + 1.0f) - 1.0f) * 0.5f);
    while ((cb + 1) * (cb + 2) / 2 <= L) cb++;
    while (cb * (cb + 1) / 2 > L) cb--;
    int rb = L - cb * (cb + 1) / 2;     /* rb <= cb */

    int t = threadIdx.x;  /* 64 */

    __shared__ float4 sbox[64];
    __shared__ float  sar[64];
    __shared__ u32    skey[64];
    __shared__ u8     sval[64];

    int cj = cb * 64 + t;
    sbox[t] = *(const float4*)(out + OFF_BOXES + ((size_t)b * NN + cj) * 4);
    sar[t]  = g_area[b][cj];
    skey[t] = g_key32[b][cj];
    sval[t] = g_validb[b][cj];
    __syncthreads();

    int i = rb * 64 + t;
    float4 rbx = *(const float4*)(out + OFF_BOXES + ((size_t)b * NN + i) * 4);
    float ar = g_area[b][i];
    u32  kr = g_key32[b][i];
    u8   rv = g_validb[b][i];

    int jstart = (rb == cb) ? (t + 1) : 0;
    for (int j = jstart; j < 64; j++) {
        float4 cx = sbox[j];
        float aj = sar[j];
        float ix1 = fmaxf(rbx.x, cx.x);
        float iy1 = fmaxf(rbx.y, cx.y);
        float ix2 = fminf(rbx.z, cx.z);
        float iy2 = fminf(rbx.w, cx.w);
        float inter = fmaxf(ix2 - ix1, 0.0f) * fmaxf(iy2 - iy1, 0.0f);
        float uni = ar + aj - inter;
        if (inter > 0.5f * fmaxf(uni, 1e-9f) && rv && sval[j]) {
            int cjj = cb * 64 + j;
            u32 kj = skey[j];
            bool jwins = (kj < kr) || (kj == kr && cjj < i);
            int victim = jwins ? i : cjj;
            int supp   = jwins ? cjj : i;
            int pos = atomicAdd(&g_cnt[b][victim], 1);
            if (pos < KCAP) g_list[b][victim][pos] = (u16)supp;
        }
    }
}

/* ------------------------------------------------------------------ */
/* Kernel 3: NMS fixed point, one block per batch, keep[] in SMEM.     */
/* Jacobi sweeps + __syncthreads; exact convergence break.             */
__global__ __launch_bounds__(1024, 1)
void nms_kernel(float* __restrict__ out)
{
    int b = blockIdx.x;
    int t = threadIdx.x;

    __shared__ u8 keep[NN];
    __shared__ int s_changed;

    u8  val[8];
    int cnt[8];
#pragma unroll
    for (int k = 0; k < 8; k++) {
        int i = t + k * 1024;
        val[k] = g_validb[b][i];
        keep[i] = val[k];
        cnt[k] = val[k] ? min(g_cnt[b][i], KCAP) : 0;
    }
    if (t == 0) s_changed = 0;
    __syncthreads();

    for (int sw = 0; sw < MAXIT; sw++) {
        bool ch = false;
#pragma unroll
        for (int k = 0; k < 8; k++) {
            int c = cnt[k];
            if (c == 0) continue;
            int i = t + k * 1024;
            const u16* lp = g_list[b][i];
            u32 s = 0;
            int q = 0;
            for (; q + 4 <= c; q += 4) {
                ushort4 v = *(const ushort4*)(lp + q);
                s |= (u32)keep[v.x] | keep[v.y] | keep[v.z] | keep[v.w];
            }
            for (; q < c; q++) s |= keep[lp[q]];
            u8 nk = (u8)(s == 0);        /* val==1 on this path */
            if (nk != keep[i]) { keep[i] = nk; ch = true; }
        }

        if (ch) s_changed = 1;
        __syncthreads();
        int stop = (s_changed == 0);
        __syncthreads();
        if (stop) break;
        if (t == 0) s_changed = 0;
        __syncthreads();
    }

    /* write keep (coalesced, original order) */
#pragma unroll
    for (int k = 0; k < 8; k++) {
        int i = t + k * 1024;
        out[OFF_KEEP + b * NN + i] = (float)keep[i];
    }
}

/* ------------------------------------------------------------------ */
extern "C" void kernel_launch(void* const* d_in, const int* in_sizes, int n_in,
                              void* d_out, int out_size)
{
    (void)in_sizes; (void)n_in; (void)out_size;
    const float* logits  = (const float*)d_in[0];
    const float* deltas  = (const float*)d_in[1];
    const float* anchors = (const float*)d_in[2];
    float* out = (float*)d_out;

    prep_kernel<<<(BB * NN * 32 + 255) / 256, 256>>>(logits, deltas, anchors, out);
    {
        int ntiles = (NN / 64) * (NN / 64 + 1) / 2;   /* 8256 */
        dim3 g(ntiles, BB);
        pairs_kernel<<<g, 64>>>(out);
    }
    nms_kernel<<<BB, 1024>>>(out);
}

// round 9
// speedup vs baseline: 1.6116x; 1.3003x over previous
#include <cuda_runtime.h>
#include <cstdint>

#define BB 2
#define NN 8192
#define CC 80
#define KCAP 128
#define MAXIT 64
#define NMSB 128      /* nms blocks (1 per SM, co-resident) */
#define NMST 128      /* nms threads per block */
#define RC 16         /* register-cached suppressors */

typedef unsigned long long u64;
typedef unsigned int u32;
typedef unsigned short u16;
typedef unsigned char u8;

/* output layout (concatenated flat float32, tuple order) */
#define OFF_BOXES 0
#define OFF_MS    (BB*NN*4)
#define OFF_LB    (OFF_MS + BB*NN)
#define OFF_KEEP  (OFF_LB + BB*NN)
#define OFF_ALL   (OFF_KEEP + BB*NN)

/* static device scratch */
__device__ u32   g_key32[BB][NN];     /* ~score_bits; smaller = higher prio */
__device__ float g_area[BB][NN];
__device__ u8    g_validb[BB][NN];
__device__ u8    g_keep[BB * NN];
__device__ int   g_cnt[BB][NN];
__device__ u16   g_list[BB][NN][KCAP];
__device__ int   g_changed[MAXIT];
__device__ u32   g_bar;

/* ------------------------------------------------------------------ */
/* Kernel 1: sigmoid / max / argmax / decode / valid (+ folded init)   */
__global__ void prep_kernel(const float* __restrict__ logits,
                            const float* __restrict__ deltas,
                            const float* __restrict__ anchors,
                            float* __restrict__ out)
{
    int wid  = (blockIdx.x * blockDim.x + threadIdx.x) >> 5;
    int lane = threadIdx.x & 31;
    if (wid >= BB * NN) return;
    int b = wid / NN, n = wid % NN;

    if (lane == 1) g_cnt[b][n] = 0;
    if (wid < MAXIT && lane == 2) g_changed[wid] = 0;
    if (wid == 0 && lane == 3) g_bar = 0u;

    const float4* lg4 = (const float4*)(logits + (size_t)wid * CC);
    float4* as4       = (float4*)(out + OFF_ALL + (size_t)wid * CC);

    float mv = -INFINITY; int mi = 0;
    if (lane < 20) {
        float4 v = lg4[lane];
        float4 s;
        s.x = __fdividef(1.0f, 1.0f + __expf(-v.x));
        s.y = __fdividef(1.0f, 1.0f + __expf(-v.y));
        s.z = __fdividef(1.0f, 1.0f + __expf(-v.z));
        s.w = __fdividef(1.0f, 1.0f + __expf(-v.w));
        as4[lane] = s;

        mv = v.x; mi = lane * 4;
        if (v.y > mv) { mv = v.y; mi = lane * 4 + 1; }
        if (v.z > mv) { mv = v.z; mi = lane * 4 + 2; }
        if (v.w > mv) { mv = v.w; mi = lane * 4 + 3; }
    }

    for (int off = 16; off; off >>= 1) {
        float ov = __shfl_down_sync(0xffffffffu, mv, off);
        int   oi = __shfl_down_sync(0xffffffffu, mi, off);
        if (ov > mv || (ov == mv && oi < mi)) { mv = ov; mi = oi; }
    }

    if (lane == 0) {
        float ms = 1.0f / (1.0f + expf(-mv));   /* accurate at threshold */
        out[OFF_MS + wid] = ms;
        out[OFF_LB + wid] = (float)mi;

        const float* dl = deltas  + (size_t)wid * 4;
        const float* an = anchors + (size_t)n * 4;
        float a0 = an[0], a1 = an[1], a2 = an[2], a3 = an[3];
        float aw = a2 - a0, ah = a3 - a1;
        float acx = a0 + 0.5f * aw, acy = a1 + 0.5f * ah;
        float dx = dl[0], dy = dl[1];
        float dw = fminf(dl[2], 4.0f), dh = fminf(dl[3], 4.0f);
        float pcx = dx * aw + acx, pcy = dy * ah + acy;
        float pw = expf(dw) * aw, ph = expf(dh) * ah;
        float x1 = fminf(fmaxf(pcx - 0.5f * pw, 0.0f), 1.0f);
        float y1 = fminf(fmaxf(pcy - 0.5f * ph, 0.0f), 1.0f);
        float x2 = fminf(fmaxf(pcx + 0.5f * pw, 0.0f), 1.0f);
        float y2 = fminf(fmaxf(pcy + 0.5f * ph, 0.0f), 1.0f);

        float* bo = out + OFF_BOXES + (size_t)wid * 4;
        bo[0] = x1; bo[1] = y1; bo[2] = x2; bo[3] = y2;

        float w = x2 - x1, h = y2 - y1;
        u8 valid = (ms > 0.5f) && (w > 0.01f) && (h > 0.01f) &&
                   (w < 0.99f) && (h < 0.99f);
        g_validb[b][n] = valid;
        g_keep[b * NN + n] = valid;          /* k0 = valid */
        g_area[b][n] = w * h;
        g_key32[b][n] = ~__float_as_uint(ms);
    }
}

/* ------------------------------------------------------------------ */
/* Kernel 2: sparse suppressor pairs, original order, straight-line.   */
__global__ void pairs_kernel(const float* __restrict__ out)
{
    int b = blockIdx.y;
    int L = blockIdx.x;
    int cb = (int)((sqrtf(8.0f * (float)L + 1.0f) - 1.0f) * 0.5f);
    while ((cb + 1) * (cb + 2) / 2 <= L) cb++;
    while (cb * (cb + 1) / 2 > L) cb--;
    int rb = L - cb * (cb + 1) / 2;     /* rb <= cb */

    int t = threadIdx.x;  /* 64 */

    __shared__ float4 sbox[64];
    __shared__ float  sar[64];
    __shared__ u32    skey[64];
    __shared__ u8     sval[64];

    int cj = cb * 64 + t;
    sbox[t] = *(const float4*)(out + OFF_BOXES + ((size_t)b * NN + cj) * 4);
    sar[t]  = g_area[b][cj];
    skey[t] = g_key32[b][cj];
    sval[t] = g_validb[b][cj];
    __syncthreads();

    int i = rb * 64 + t;
    float4 rbx = *(const float4*)(out + OFF_BOXES + ((size_t)b * NN + i) * 4);
    float ar = g_area[b][i];
    u32  kr = g_key32[b][i];
    u8   rv = g_validb[b][i];

    int jstart = (rb == cb) ? (t + 1) : 0;
    for (int j = jstart; j < 64; j++) {
        float4 cx = sbox[j];
        float aj = sar[j];
        float ix1 = fmaxf(rbx.x, cx.x);
        float iy1 = fmaxf(rbx.y, cx.y);
        float ix2 = fminf(rbx.z, cx.z);
        float iy2 = fminf(rbx.w, cx.w);
        float inter = fmaxf(ix2 - ix1, 0.0f) * fmaxf(iy2 - iy1, 0.0f);
        float uni = ar + aj - inter;
        if (inter > 0.5f * fmaxf(uni, 1e-9f) && rv && sval[j]) {
            int cjj = cb * 64 + j;
            u32 kj = skey[j];
            bool jwins = (kj < kr) || (kj == kr && cjj < i);
            int victim = jwins ? i : cjj;
            int supp   = jwins ? cjj : i;
            int pos = atomicAdd(&g_cnt[b][victim], 1);
            if (pos < KCAP) g_list[b][victim][pos] = (u16)supp;
        }
    }
}

/* ------------------------------------------------------------------ */
/* Kernel 3: NMS fixed point. 128 blocks x 128 threads, 1 thread/box.  */
/* L2-coherent keep via ldcg/stcg; grid barrier; exact convergence.    */
__global__ __launch_bounds__(NMST, 1)
void nms_kernel(float* __restrict__ out)
{
    int tid = blockIdx.x * NMST + threadIdx.x;   /* 0 .. 16383 */
    int b = tid >> 13;
    int i = tid & (NN - 1);
    int base = b * NN;

    u8 valid = g_validb[b][i];
    int cnt = valid ? min(g_cnt[b][i], KCAP) : 0;
    const u16* lp = g_list[b][i];

    /* register-cache first RC suppressor flat addresses */
    int lf[RC];
#pragma unroll
    for (int q = 0; q < RC; q++) lf[q] = base;
    int nr = min(cnt, RC);
    for (int q = 0; q < nr; q++) lf[q] = base + (int)lp[q];

    __shared__ int s_stop;
    u32 tgt = 0;
    u8 cur = valid;

    for (int it = 0; it < MAXIT; it++) {
        bool ch = false;
        if (cnt > 0) {
            u32 s = 0;
#pragma unroll
            for (int q = 0; q < RC; q++)
                if (q < cnt) s |= __ldcg(&g_keep[lf[q]]);
            for (int q = RC; q < cnt; q++)
                s |= __ldcg(&g_keep[base + (int)lp[q]]);
            u8 nk = (u8)(s == 0);          /* valid==1 on this path */
            if (nk != cur) { cur = nk; __stcg(&g_keep[base + i], nk); ch = true; }
        }

        u32 w = __ballot_sync(0xffffffffu, ch);
        if ((threadIdx.x & 31) == 0 && w) atomicExch(&g_changed[it], 1);
        __threadfence();
        __syncthreads();

        tgt += NMSB;
        if (threadIdx.x == 0) {
            atomicAdd(&g_bar, 1u);
            while (*((volatile u32*)&g_bar) < tgt) { }
            s_stop = (atomicAdd(&g_changed[it], 0) == 0);
        }
        __syncthreads();
        if (s_stop) break;
    }

    out[OFF_KEEP + base + i] = (float)cur;
}

/* ------------------------------------------------------------------ */
extern "C" void kernel_launch(void* const* d_in, const int* in_sizes, int n_in,
                              void* d_out, int out_size)
{
    (void)in_sizes; (void)n_in; (void)out_size;
    const float* logits  = (const float*)d_in[0];
    const float* deltas  = (const float*)d_in[1];
    const float* anchors = (const float*)d_in[2];
    float* out = (float*)d_out;

    prep_kernel<<<(BB * NN * 32 + 255) / 256, 256>>>(logits, deltas, anchors, out);
    {
        int ntiles = (NN / 64) * (NN / 64 + 1) / 2;   /* 8256 */
        dim3 g(ntiles, BB);
        pairs_kernel<<<g, 64>>>(out);
    }
    nms_kernel<<<NMSB, NMST>>>(out);
}

// round 10
// speedup vs baseline: 1.6869x; 1.0468x over previous
#include <cuda_runtime.h>
#include <cstdint>

#define BB 2
#define NN 8192
#define CC 80
#define KCAP 128
#define MAXIT 64
#define CELLS 256        /* 16x16 spatial cells */
#define NT (NN/64)       /* 128 tiles per batch */
#define NMSB 32
#define NMST 512
#define RC 16

typedef unsigned long long u64;
typedef unsigned int u32;
typedef unsigned short u16;
typedef unsigned char u8;

/* output layout (concatenated flat float32, tuple order) */
#define OFF_BOXES 0
#define OFF_MS    (BB*NN*4)
#define OFF_LB    (OFF_MS + BB*NN)
#define OFF_KEEP  (OFF_LB + BB*NN)
#define OFF_ALL   (OFF_KEEP + BB*NN)

/* static device scratch */
__device__ u32    g_key32[BB][NN];      /* ~score_bits (original order) */
__device__ u8     g_validb[BB][NN];
__device__ u8     g_cell[BB][NN];
__device__ int    g_off[BB][CELLS];
__device__ u16    g_perm[BB][NN];       /* sorted pos -> original idx */
__device__ float4 g_sbox[BB][NN];
__device__ float  g_sarea[BB][NN];
__device__ u32    g_skey[BB][NN];
__device__ u8     g_sval[BB][NN];
__device__ u16    g_sperm[BB][NN];
__device__ float4 g_taabb[BB][NT];
__device__ u8     g_keep[BB * NN];      /* sorted space */
__device__ int    g_cnt[BB][NN];        /* sorted space */
__device__ u16    g_list[BB][NN][KCAP]; /* sorted space */
__device__ int    g_changed[MAXIT];
__device__ u32    g_bar;

/* ------------------------------------------------------------------ */
/* Kernel 1: sigmoid / max / argmax / decode / valid / cell (+init)    */
__global__ void prep_kernel(const float* __restrict__ logits,
                            const float* __restrict__ deltas,
                            const float* __restrict__ anchors,
                            float* __restrict__ out)
{
    int wid  = (blockIdx.x * blockDim.x + threadIdx.x) >> 5;
    int lane = threadIdx.x & 31;
    if (wid >= BB * NN) return;
    int b = wid / NN, n = wid % NN;

    if (lane == 1) g_cnt[b][n] = 0;
    if (wid < MAXIT && lane == 2) g_changed[wid] = 0;
    if (wid == 0 && lane == 3) g_bar = 0u;

    const float4* lg4 = (const float4*)(logits + (size_t)wid * CC);
    float4* as4       = (float4*)(out + OFF_ALL + (size_t)wid * CC);

    float mv = -INFINITY; int mi = 0;
    if (lane < 20) {
        float4 v = lg4[lane];
        float4 s;
        s.x = __fdividef(1.0f, 1.0f + __expf(-v.x));
        s.y = __fdividef(1.0f, 1.0f + __expf(-v.y));
        s.z = __fdividef(1.0f, 1.0f + __expf(-v.z));
        s.w = __fdividef(1.0f, 1.0f + __expf(-v.w));
        as4[lane] = s;

        mv = v.x; mi = lane * 4;
        if (v.y > mv) { mv = v.y; mi = lane * 4 + 1; }
        if (v.z > mv) { mv = v.z; mi = lane * 4 + 2; }
        if (v.w > mv) { mv = v.w; mi = lane * 4 + 3; }
    }

    for (int off = 16; off; off >>= 1) {
        float ov = __shfl_down_sync(0xffffffffu, mv, off);
        int   oi = __shfl_down_sync(0xffffffffu, mi, off);
        if (ov > mv || (ov == mv && oi < mi)) { mv = ov; mi = oi; }
    }

    if (lane == 0) {
        float ms = 1.0f / (1.0f + expf(-mv));   /* accurate at threshold */
        out[OFF_MS + wid] = ms;
        out[OFF_LB + wid] = (float)mi;

        const float* dl = deltas  + (size_t)wid * 4;
        const float* an = anchors + (size_t)n * 4;
        float a0 = an[0], a1 = an[1], a2 = an[2], a3 = an[3];
        float aw = a2 - a0, ah = a3 - a1;
        float acx = a0 + 0.5f * aw, acy = a1 + 0.5f * ah;
        float dx = dl[0], dy = dl[1];
        float dw = fminf(dl[2], 4.0f), dh = fminf(dl[3], 4.0f);
        float pcx = dx * aw + acx, pcy = dy * ah + acy;
        float pw = expf(dw) * aw, ph = expf(dh) * ah;
        float x1 = fminf(fmaxf(pcx - 0.5f * pw, 0.0f), 1.0f);
        float y1 = fminf(fmaxf(pcy - 0.5f * ph, 0.0f), 1.0f);
        float x2 = fminf(fmaxf(pcx + 0.5f * pw, 0.0f), 1.0f);
        float y2 = fminf(fmaxf(pcy + 0.5f * ph, 0.0f), 1.0f);

        float* bo = out + OFF_BOXES + (size_t)wid * 4;
        bo[0] = x1; bo[1] = y1; bo[2] = x2; bo[3] = y2;

        float w = x2 - x1, h = y2 - y1;
        u8 valid = (ms > 0.5f) && (w > 0.01f) && (h > 0.01f) &&
                   (w < 0.99f) && (h < 0.99f);
        g_validb[b][n] = valid;
        g_key32[b][n] = ~__float_as_uint(ms);

        int ix = min(15, max(0, (int)((x1 + x2) * 8.0f)));
        int iy = min(15, max(0, (int)((y1 + y2) * 8.0f)));
        g_cell[b][n] = (u8)(ix * 16 + iy);
    }
}

/* ------------------------------------------------------------------ */
/* Kernel 2: per-batch cell histogram (smem) + exclusive prefix        */
__global__ void prefix_kernel()
{
    int b = blockIdx.x;
    int t = threadIdx.x;   /* 256 */
    __shared__ int s[CELLS];
    s[t] = 0;
    __syncthreads();
    for (int i = t; i < NN; i += 256)
        atomicAdd(&s[g_cell[b][i]], 1);
    __syncthreads();
    int my = s[t];
    __syncthreads();
    /* Hillis-Steele inclusive scan */
    for (int off = 1; off < CELLS; off <<= 1) {
        int v = (t >= off) ? s[t - off] : 0;
        __syncthreads();
        s[t] += v;
        __syncthreads();
    }
    g_off[b][t] = s[t] - my;   /* exclusive */
}

/* ------------------------------------------------------------------ */
/* Kernel 3: scatter into sorted (cell-grouped) arrays                 */
__global__ void scatter_kernel(const float* __restrict__ out)
{
    int idx = blockIdx.x * blockDim.x + threadIdx.x;
    if (idx >= BB * NN) return;
    int b = idx / NN, n = idx % NN;

    u8 cell = g_cell[b][n];
    int pos = atomicAdd(&g_off[b][cell], 1);
    g_perm[b][pos]  = (u16)n;
    g_sperm[b][pos] = (u16)n;
    float4 bx = *(const float4*)(out + OFF_BOXES + ((size_t)b * NN + n) * 4);
    g_sbox[b][pos]  = bx;
    g_sarea[b][pos] = (bx.z - bx.x) * (bx.w - bx.y);
    g_skey[b][pos]  = g_key32[b][n];
    u8 v = g_validb[b][n];
    g_sval[b][pos]  = v;
    g_keep[b * NN + pos] = v;
}

/* ------------------------------------------------------------------ */
/* Kernel 4: per-tile AABB                                             */
__global__ void taabb_kernel()
{
    int b = blockIdx.y, tile = blockIdx.x;
    int t = threadIdx.x;   /* 64 */
    float4 bx = g_sbox[b][tile * 64 + t];
    float mnx = bx.x, mny = bx.y, mxx = bx.z, mxy = bx.w;
    for (int off = 16; off; off >>= 1) {
        mnx = fminf(mnx, __shfl_xor_sync(0xffffffffu, mnx, off));
        mny = fminf(mny, __shfl_xor_sync(0xffffffffu, mny, off));
        mxx = fmaxf(mxx, __shfl_xor_sync(0xffffffffu, mxx, off));
        mxy = fmaxf(mxy, __shfl_xor_sync(0xffffffffu, mxy, off));
    }
    __shared__ float4 w0;
    if (t == 0) w0 = make_float4(mnx, mny, mxx, mxy);
    __syncthreads();
    if (t == 32)
        g_taabb[b][tile] = make_float4(fminf(mnx, w0.x), fminf(mny, w0.y),
                                       fmaxf(mxx, w0.z), fmaxf(mxy, w0.w));
}

/* ------------------------------------------------------------------ */
/* Kernel 5: pairs over sorted tiles; AABB prune; smem-accumulated     */
/* suppressor lists flushed with one bulk atomic per victim per block. */
__global__ void pairs_kernel()
{
    int b = blockIdx.y;
    int L = blockIdx.x;
    int cb = (int)((sqrtf(8.0f * (float)L + 1.0f) - 1.0f) * 0.5f);
    while ((cb + 1) * (cb + 2) / 2 <= L) cb++;
    while (cb * (cb + 1) / 2 > L) cb--;
    int rb = L - cb * (cb + 1) / 2;     /* rb <= cb */

    /* tile-level AABB prune (exact necessary condition for inter>0) */
    float4 ra = g_taabb[b][rb];
    float4 ca = g_taabb[b][cb];
    if (!(fminf(ra.z, ca.z) > fmaxf(ra.x, ca.x) &&
          fminf(ra.w, ca.w) > fmaxf(ra.y, ca.y)))
        return;

    int t = threadIdx.x;  /* 64 */

    __shared__ float4 sbox[64];
    __shared__ float  sar[64];
    __shared__ u32    skey[64];
    __shared__ u8     sval[64];
    __shared__ u16    spr[64];
    __shared__ u32    lcnt[128];        /* 0..63 row victims, 64..127 col */
    __shared__ u16    llist[128 * 64];  /* 16 KB */

    int cj = cb * 64 + t;
    sbox[t] = g_sbox[b][cj];
    sar[t]  = g_sarea[b][cj];
    skey[t] = g_skey[b][cj];
    sval[t] = g_sval[b][cj];
    spr[t]  = g_sperm[b][cj];
    lcnt[t] = 0; lcnt[t + 64] = 0;
    __syncthreads();

    int i = rb * 64 + t;
    float4 rbx = g_sbox[b][i];
    float ar = g_sarea[b][i];
    u32  kr = g_skey[b][i];
    u8   rv = g_sval[b][i];
    u16  rp = g_sperm[b][i];

    /* row-level prune vs col tile AABB */
    bool active = (fminf(rbx.z, ca.z) > fmaxf(rbx.x, ca.x) &&
                   fminf(rbx.w, ca.w) > fmaxf(rbx.y, ca.y));

    if (active) {
        int jstart = (rb == cb) ? (t + 1) : 0;
        u32 rowc = 0;
        for (int j = jstart; j < 64; j++) {
            float4 cx = sbox[j];
            float aj = sar[j];
            float ix1 = fmaxf(rbx.x, cx.x);
            float iy1 = fmaxf(rbx.y, cx.y);
            float ix2 = fminf(rbx.z, cx.z);
            float iy2 = fminf(rbx.w, cx.w);
            float inter = fmaxf(ix2 - ix1, 0.0f) * fmaxf(iy2 - iy1, 0.0f);
            float uni = ar + aj - inter;
            if (inter > 0.5f * fmaxf(uni, 1e-9f) && rv && sval[j]) {
                u32 kj = skey[j];
                bool jwins = (kj < kr) || (kj == kr && spr[j] < rp);
                if (jwins) {
                    /* victim = my row box: private slot t */
                    llist[t * 64 + rowc] = (u16)(cb * 64 + j);
                    rowc++;
                } else {
                    /* victim = col box j: shared slot 64+j */
                    u32 p = atomicAdd(&lcnt[64 + j], 1u);
                    llist[(64 + j) * 64 + p] = (u16)i;
                }
            }
        }
        lcnt[t] = rowc;
    }
    __syncthreads();

    /* bulk flush: one global atomic per non-empty victim slot */
#pragma unroll
    for (int s = t; s < 128; s += 64) {
        int c = (int)lcnt[s];
        if (c > 0) {
            int victim = (s < 64) ? (rb * 64 + s) : (cb * 64 + (s - 64));
            int pos = atomicAdd(&g_cnt[b][victim], c);
            for (int q = 0; q < c && pos + q < KCAP; q++)
                g_list[b][victim][pos + q] = llist[s * 64 + q];
        }
    }
}

/* ------------------------------------------------------------------ */
/* Kernel 6: NMS fixed point, 32 blocks x 512, sorted space.           */
__global__ __launch_bounds__(NMST, 1)
void nms_kernel(float* __restrict__ out)
{
    int tid = blockIdx.x * NMST + threadIdx.x;   /* 0 .. 16383 */
    int b = tid >> 13;
    int i = tid & (NN - 1);
    int base = b * NN;

    u8 valid = g_sval[b][i];
    int cnt = valid ? min(g_cnt[b][i], KCAP) : 0;
    const u16* lp = g_list[b][i];

    int lf[RC];
#pragma unroll
    for (int q = 0; q < RC; q++) lf[q] = base;
    int nr = min(cnt, RC);
    for (int q = 0; q < nr; q++) lf[q] = base + (int)lp[q];

    __shared__ int s_stop;
    u32 tgt = 0;
    u8 cur = valid;

    for (int it = 0; it < MAXIT; it++) {
        bool ch = false;
        if (cnt > 0) {
#pragma unroll
            for (int rep = 0; rep < 2; rep++) {
                u32 s = 0;
#pragma unroll
                for (int q = 0; q < RC; q++)
                    if (q < cnt) s |= __ldcg(&g_keep[lf[q]]);
                for (int q = RC; q < cnt; q++)
                    s |= __ldcg(&g_keep[base + (int)lp[q]]);
                u8 nk = (u8)(s == 0);
                if (nk != cur) { cur = nk; __stcg(&g_keep[base + i], nk); ch = true; }
            }
        }

        u32 w = __ballot_sync(0xffffffffu, ch);
        if ((threadIdx.x & 31) == 0 && w) atomicExch(&g_changed[it], 1);
        __threadfence();
        __syncthreads();

        tgt += NMSB;
        if (threadIdx.x == 0) {
            atomicAdd(&g_bar, 1u);
            while (*((volatile u32*)&g_bar) < tgt) { }
            s_stop = (atomicAdd(&g_changed[it], 0) == 0);
        }
        __syncthreads();
        if (s_stop) break;
    }

    out[OFF_KEEP + base + (int)g_perm[b][i]] = (float)cur;
}

/* ------------------------------------------------------------------ */
extern "C" void kernel_launch(void* const* d_in, const int* in_sizes, int n_in,
                              void* d_out, int out_size)
{
    (void)in_sizes; (void)n_in; (void)out_size;
    const float* logits  = (const float*)d_in[0];
    const float* deltas  = (const float*)d_in[1];
    const float* anchors = (const float*)d_in[2];
    float* out = (float*)d_out;

    prep_kernel<<<(BB * NN * 32 + 255) / 256, 256>>>(logits, deltas, anchors, out);
    prefix_kernel<<<BB, CELLS>>>();
    scatter_kernel<<<(BB * NN + 255) / 256, 256>>>(out);
    {
        dim3 g(NT, BB);
        taabb_kernel<<<g, 64>>>();
    }
    {
        dim3 g(NT * (NT + 1) / 2, BB);
        pairs_kernel<<<g, 64>>>();
    }
    nms_kernel<<<NMSB, NMST>>>(out);
}

// round 11
// speedup vs baseline: 1.7505x; 1.0377x over previous
#include <cuda_runtime.h>
#include <cstdint>

#define BB 2
#define NN 8192
#define CC 80
#define KCAP 128
#define MAXIT 64
#define CELLS 256        /* 16x16 spatial cells */
#define NT (NN/64)       /* 128 tiles per batch */
#define NMSB 32
#define NMST 512
#define RC 16

typedef unsigned long long u64;
typedef unsigned int u32;
typedef unsigned short u16;
typedef unsigned char u8;

/* output layout (concatenated flat float32, tuple order) */
#define OFF_BOXES 0
#define OFF_MS    (BB*NN*4)
#define OFF_LB    (OFF_MS + BB*NN)
#define OFF_KEEP  (OFF_LB + BB*NN)
#define OFF_ALL   (OFF_KEEP + BB*NN)

/* static device scratch */
__device__ u32    g_key32[BB][NN];      /* ~score_bits (original order) */
__device__ u8     g_validb[BB][NN];
__device__ u8     g_cell[BB][NN];
__device__ int    g_off[BB][CELLS];
__device__ u16    g_perm[BB][NN];       /* sorted pos -> original idx */
__device__ float4 g_sbox[BB][NN];
__device__ float  g_sarea[BB][NN];
__device__ u32    g_skey[BB][NN];
__device__ u8     g_sval[BB][NN];
__device__ float4 g_taabb[BB][NT];
__device__ u8     g_keep[BB * NN];      /* sorted space */
__device__ int    g_cnt[BB][NN];        /* sorted space */
__device__ u16    g_list[BB][NN][KCAP]; /* sorted space */
__device__ int    g_changed[MAXIT];
__device__ u32    g_bar;

/* ------------------------------------------------------------------ */
/* Kernel 1: sigmoid / max / argmax / decode / valid / cell (+init)    */
__global__ void prep_kernel(const float* __restrict__ logits,
                            const float* __restrict__ deltas,
                            const float* __restrict__ anchors,
                            float* __restrict__ out)
{
    int wid  = (blockIdx.x * blockDim.x + threadIdx.x) >> 5;
    int lane = threadIdx.x & 31;
    if (wid >= BB * NN) return;
    int b = wid / NN, n = wid % NN;

    if (lane == 1) g_cnt[b][n] = 0;
    if (wid < MAXIT && lane == 2) g_changed[wid] = 0;
    if (wid == 0 && lane == 3) g_bar = 0u;

    const float4* lg4 = (const float4*)(logits + (size_t)wid * CC);
    float4* as4       = (float4*)(out + OFF_ALL + (size_t)wid * CC);

    float mv = -INFINITY; int mi = 0;
    if (lane < 20) {
        float4 v = lg4[lane];
        float4 s;
        s.x = __fdividef(1.0f, 1.0f + __expf(-v.x));
        s.y = __fdividef(1.0f, 1.0f + __expf(-v.y));
        s.z = __fdividef(1.0f, 1.0f + __expf(-v.z));
        s.w = __fdividef(1.0f, 1.0f + __expf(-v.w));
        as4[lane] = s;

        mv = v.x; mi = lane * 4;
        if (v.y > mv) { mv = v.y; mi = lane * 4 + 1; }
        if (v.z > mv) { mv = v.z; mi = lane * 4 + 2; }
        if (v.w > mv) { mv = v.w; mi = lane * 4 + 3; }
    }

    for (int off = 16; off; off >>= 1) {
        float ov = __shfl_down_sync(0xffffffffu, mv, off);
        int   oi = __shfl_down_sync(0xffffffffu, mi, off);
        if (ov > mv || (ov == mv && oi < mi)) { mv = ov; mi = oi; }
    }

    if (lane == 0) {
        float ms = 1.0f / (1.0f + expf(-mv));   /* accurate at threshold */
        out[OFF_MS + wid] = ms;
        out[OFF_LB + wid] = (float)mi;

        const float* dl = deltas  + (size_t)wid * 4;
        const float* an = anchors + (size_t)n * 4;
        float a0 = an[0], a1 = an[1], a2 = an[2], a3 = an[3];
        float aw = a2 - a0, ah = a3 - a1;
        float acx = a0 + 0.5f * aw, acy = a1 + 0.5f * ah;
        float dx = dl[0], dy = dl[1];
        float dw = fminf(dl[2], 4.0f), dh = fminf(dl[3], 4.0f);
        float pcx = dx * aw + acx, pcy = dy * ah + acy;
        float pw = expf(dw) * aw, ph = expf(dh) * ah;
        float x1 = fminf(fmaxf(pcx - 0.5f * pw, 0.0f), 1.0f);
        float y1 = fminf(fmaxf(pcy - 0.5f * ph, 0.0f), 1.0f);
        float x2 = fminf(fmaxf(pcx + 0.5f * pw, 0.0f), 1.0f);
        float y2 = fminf(fmaxf(pcy + 0.5f * ph, 0.0f), 1.0f);

        float* bo = out + OFF_BOXES + (size_t)wid * 4;
        bo[0] = x1; bo[1] = y1; bo[2] = x2; bo[3] = y2;

        float w = x2 - x1, h = y2 - y1;
        u8 valid = (ms > 0.5f) && (w > 0.01f) && (h > 0.01f) &&
                   (w < 0.99f) && (h < 0.99f);
        g_validb[b][n] = valid;
        g_key32[b][n] = ~__float_as_uint(ms);

        int ix = min(15, max(0, (int)((x1 + x2) * 8.0f)));
        int iy = min(15, max(0, (int)((y1 + y2) * 8.0f)));
        g_cell[b][n] = (u8)(ix * 16 + iy);
    }
}

/* ------------------------------------------------------------------ */
/* Kernel 2: per-batch cell histogram (smem) + exclusive prefix        */
__global__ void prefix_kernel()
{
    int b = blockIdx.x;
    int t = threadIdx.x;   /* 256 */
    __shared__ int s[CELLS];
    s[t] = 0;
    __syncthreads();
    for (int i = t; i < NN; i += 256)
        atomicAdd(&s[g_cell[b][i]], 1);
    __syncthreads();
    int my = s[t];
    __syncthreads();
    for (int off = 1; off < CELLS; off <<= 1) {
        int v = (t >= off) ? s[t - off] : 0;
        __syncthreads();
        s[t] += v;
        __syncthreads();
    }
    g_off[b][t] = s[t] - my;   /* exclusive */
}

/* ------------------------------------------------------------------ */
/* Kernel 3: scatter into sorted (cell-grouped) arrays                 */
__global__ void scatter_kernel(const float* __restrict__ out)
{
    int idx = blockIdx.x * blockDim.x + threadIdx.x;
    if (idx >= BB * NN) return;
    int b = idx / NN, n = idx % NN;

    u8 cell = g_cell[b][n];
    int pos = atomicAdd(&g_off[b][cell], 1);
    g_perm[b][pos] = (u16)n;
    float4 bx = *(const float4*)(out + OFF_BOXES + ((size_t)b * NN + n) * 4);
    g_sbox[b][pos]  = bx;
    g_sarea[b][pos] = (bx.z - bx.x) * (bx.w - bx.y);
    g_skey[b][pos]  = g_key32[b][n];
    u8 v = g_validb[b][n];
    g_sval[b][pos]  = v;
    g_keep[b * NN + pos] = v;
}

/* ------------------------------------------------------------------ */
/* Kernel 4: per-tile AABB, one warp per tile                          */
__global__ void taabb_kernel()
{
    int gw   = (blockIdx.x * blockDim.x + threadIdx.x) >> 5;
    int lane = threadIdx.x & 31;
    if (gw >= BB * NT) return;
    int b = gw / NT, tile = gw % NT;

    float4 b0 = g_sbox[b][tile * 64 + lane];
    float4 b1 = g_sbox[b][tile * 64 + 32 + lane];
    float mnx = fminf(b0.x, b1.x), mny = fminf(b0.y, b1.y);
    float mxx = fmaxf(b0.z, b1.z), mxy = fmaxf(b0.w, b1.w);
    for (int off = 16; off; off >>= 1) {
        mnx = fminf(mnx, __shfl_xor_sync(0xffffffffu, mnx, off));
        mny = fminf(mny, __shfl_xor_sync(0xffffffffu, mny, off));
        mxx = fmaxf(mxx, __shfl_xor_sync(0xffffffffu, mxx, off));
        mxy = fmaxf(mxy, __shfl_xor_sync(0xffffffffu, mxy, off));
    }
    if (lane == 0)
        g_taabb[b][tile] = make_float4(mnx, mny, mxx, mxy);
}

/* ------------------------------------------------------------------ */
/* Kernel 5: pairs over sorted tiles; AABB prune; smem-accumulated     */
/* suppressor lists flushed with one bulk atomic per victim per block. */
__global__ void pairs_kernel()
{
    int b = blockIdx.y;
    int L = blockIdx.x;
    int cb = (int)((sqrtf(8.0f * (float)L + 1.0f) - 1.0f) * 0.5f);
    while ((cb + 1) * (cb + 2) / 2 <= L) cb++;
    while (cb * (cb + 1) / 2 > L) cb--;
    int rb = L - cb * (cb + 1) / 2;     /* rb <= cb */

    float4 ra = g_taabb[b][rb];
    float4 ca = g_taabb[b][cb];
    if (!(fminf(ra.z, ca.z) > fmaxf(ra.x, ca.x) &&
          fminf(ra.w, ca.w) > fmaxf(ra.y, ca.y)))
        return;

    int t = threadIdx.x;  /* 64 */

    __shared__ float4 sbox[64];
    __shared__ float  sar[64];
    __shared__ u32    skey[64];
    __shared__ u8     sval[64];
    __shared__ u16    spr[64];
    __shared__ u32    lcnt[128];        /* 0..63 row victims, 64..127 col */
    __shared__ u16    llist[128 * 64];  /* 16 KB */

    int cj = cb * 64 + t;
    sbox[t] = g_sbox[b][cj];
    sar[t]  = g_sarea[b][cj];
    skey[t] = g_skey[b][cj];
    sval[t] = g_sval[b][cj];
    spr[t]  = g_perm[b][cj];
    lcnt[t] = 0; lcnt[t + 64] = 0;
    __syncthreads();

    int i = rb * 64 + t;
    float4 rbx = g_sbox[b][i];
    float ar = g_sarea[b][i];
    u32  kr = g_skey[b][i];
    u8   rv = g_sval[b][i];
    u16  rp = g_perm[b][i];

    bool active = (fminf(rbx.z, ca.z) > fmaxf(rbx.x, ca.x) &&
                   fminf(rbx.w, ca.w) > fmaxf(rbx.y, ca.y));

    if (active) {
        int jstart = (rb == cb) ? (t + 1) : 0;
        u32 rowc = 0;
        for (int j = jstart; j < 64; j++) {
            float4 cx = sbox[j];
            float aj = sar[j];
            float ix1 = fmaxf(rbx.x, cx.x);
            float iy1 = fmaxf(rbx.y, cx.y);
            float ix2 = fminf(rbx.z, cx.z);
            float iy2 = fminf(rbx.w, cx.w);
            float inter = fmaxf(ix2 - ix1, 0.0f) * fmaxf(iy2 - iy1, 0.0f);
            float uni = ar + aj - inter;
            if (inter > 0.5f * fmaxf(uni, 1e-9f) && rv && sval[j]) {
                u32 kj = skey[j];
                bool jwins = (kj < kr) || (kj == kr && spr[j] < rp);
                if (jwins) {
                    llist[t * 64 + rowc] = (u16)(cb * 64 + j);
                    rowc++;
                } else {
                    u32 p = atomicAdd(&lcnt[64 + j], 1u);
                    llist[(64 + j) * 64 + p] = (u16)i;
                }
            }
        }
        lcnt[t] = rowc;
    }
    __syncthreads();

#pragma unroll
    for (int s = t; s < 128; s += 64) {
        int c = (int)lcnt[s];
        if (c > 0) {
            int victim = (s < 64) ? (rb * 64 + s) : (cb * 64 + (s - 64));
            int pos = atomicAdd(&g_cnt[b][victim], c);
            for (int q = 0; q < c && pos + q < KCAP; q++)
                g_list[b][victim][pos + q] = llist[s * 64 + q];
        }
    }
}

/* ------------------------------------------------------------------ */
/* Kernel 6: NMS fixed point, 32 blocks x 512, sorted space.           */
/* Change flag: smem-reduced, ONE global atomic per block per sweep.   */
__global__ __launch_bounds__(NMST, 1)
void nms_kernel(float* __restrict__ out)
{
    int tid = blockIdx.x * NMST + threadIdx.x;   /* 0 .. 16383 */
    int b = tid >> 13;
    int i = tid & (NN - 1);
    int base = b * NN;

    u8 valid = g_sval[b][i];
    int cnt = valid ? min(g_cnt[b][i], KCAP) : 0;
    const u16* lp = g_list[b][i];

    int lf[RC];
#pragma unroll
    for (int q = 0; q < RC; q++) lf[q] = base;
    int nr = min(cnt, RC);
    for (int q = 0; q < nr; q++) lf[q] = base + (int)lp[q];

    __shared__ int s_stop;
    __shared__ int s_any;
    u32 tgt = 0;
    u8 cur = valid;

    for (int it = 0; it < MAXIT; it++) {
        if (threadIdx.x == 0) s_any = 0;
        __syncthreads();

        bool ch = false;
        if (cnt > 0) {
#pragma unroll
            for (int rep = 0; rep < 2; rep++) {
                u32 s = 0;
#pragma unroll
                for (int q = 0; q < RC; q++)
                    if (q < cnt) s |= __ldcg(&g_keep[lf[q]]);
                for (int q = RC; q < cnt; q++)
                    s |= __ldcg(&g_keep[base + (int)lp[q]]);
                u8 nk = (u8)(s == 0);
                if (nk != cur) { cur = nk; __stcg(&g_keep[base + i], nk); ch = true; }
            }
        }

        u32 w = __ballot_sync(0xffffffffu, ch);
        if ((threadIdx.x & 31) == 0 && w) s_any = 1;   /* plain smem write */
        if (ch) __threadfence();                        /* order keep stores */
        __syncthreads();

        tgt += NMSB;
        if (threadIdx.x == 0) {
            if (s_any) atomicExch(&g_changed[it], 1);   /* 1 atomic / block */
            atomicAdd(&g_bar, 1u);
            while (*((volatile u32*)&g_bar) < tgt) { }
            s_stop = (atomicAdd(&g_changed[it], 0) == 0);
        }
        __syncthreads();
        if (s_stop) break;
    }

    out[OFF_KEEP + base + (int)g_perm[b][i]] = (float)cur;
}

/* ------------------------------------------------------------------ */
extern "C" void kernel_launch(void* const* d_in, const int* in_sizes, int n_in,
                              void* d_out, int out_size)
{
    (void)in_sizes; (void)n_in; (void)out_size;
    const float* logits  = (const float*)d_in[0];
    const float* deltas  = (const float*)d_in[1];
    const float* anchors = (const float*)d_in[2];
    float* out = (float*)d_out;

    prep_kernel<<<(BB * NN * 32 + 255) / 256, 256>>>(logits, deltas, anchors, out);
    prefix_kernel<<<BB, CELLS>>>();
    scatter_kernel<<<(BB * NN + 255) / 256, 256>>>(out);
    taabb_kernel<<<(BB * NT * 32 + 1023) / 1024, 1024>>>();
    {
        dim3 g(NT * (NT + 1) / 2, BB);
        pairs_kernel<<<g, 64>>>();
    }
    nms_kernel<<<NMSB, NMST>>>(out);
}